// round 16
// baseline (speedup 1.0000x reference)
#include <cuda_runtime.h>
#include <cuda_fp16.h>
#include <cstdint>

// ---------------- problem constants ----------------
#define HH    96
#define WWID  96
#define HWSZ  (HH * WWID)      // 9216
#define BATCH 8
#define CIN   256
#define ACH   128
#define KWIN  7
#define NOFF  (KWIN * KWIN)    // 49
#define NPIX  (BATCH * HWSZ)   // 73728

// q scratch fp16 hi/lo; k scratch fp16 hi only
__device__ __half g_qh[(size_t)NPIX * ACH];
__device__ __half g_ql[(size_t)NPIX * ACH];
__device__ __half g_kh[(size_t)NPIX * ACH];

// W split into fp16 hi/lo, rows 0-127 = w_q, rows 128-255 = w_k
__device__ __half g_wh[256][256];
__device__ __half g_wl[256][256];

// ---------------- helpers ----------------
__device__ __forceinline__ uint32_t smem_u32(const void* p) {
    uint32_t a;
    asm("{ .reg .u64 t; cvta.to.shared.u64 t, %1; cvt.u32.u64 %0, t; }"
        : "=r"(a) : "l"(p));
    return a;
}

__device__ __forceinline__ uint32_t pack2(__half a, __half b) {
    return (uint32_t)__half_as_ushort(a) | ((uint32_t)__half_as_ushort(b) << 16);
}

__device__ __forceinline__ void split4(float4 v, uint2& hi, uint2& lo) {
    __half h0 = __float2half_rn(v.x), h1 = __float2half_rn(v.y);
    __half h2 = __float2half_rn(v.z), h3 = __float2half_rn(v.w);
    __half l0 = __float2half_rn(v.x - __half2float(h0));
    __half l1 = __float2half_rn(v.y - __half2float(h1));
    __half l2 = __float2half_rn(v.z - __half2float(h2));
    __half l3 = __float2half_rn(v.w - __half2float(h3));
    hi = make_uint2(pack2(h0, h1), pack2(h2, h3));
    lo = make_uint2(pack2(l0, l1), pack2(l2, l3));
}
__device__ __forceinline__ uint2 hi4(float4 v) {
    return make_uint2(pack2(__float2half_rn(v.x), __float2half_rn(v.y)),
                      pack2(__float2half_rn(v.z), __float2half_rn(v.w)));
}

__device__ __forceinline__ void ldsm_x4(uint32_t* r, uint32_t addr) {
    asm volatile("ldmatrix.sync.aligned.m8n8.x4.shared.b16 {%0,%1,%2,%3}, [%4];"
                 : "=r"(r[0]), "=r"(r[1]), "=r"(r[2]), "=r"(r[3]) : "r"(addr));
}
__device__ __forceinline__ void ldsm_x4t(uint32_t* r, uint32_t addr) {
    asm volatile("ldmatrix.sync.aligned.m8n8.x4.trans.shared.b16 {%0,%1,%2,%3}, [%4];"
                 : "=r"(r[0]), "=r"(r[1]), "=r"(r[2]), "=r"(r[3]) : "r"(addr));
}
__device__ __forceinline__ void mma_f32(float* d, const uint32_t* a, const uint32_t* b) {
    asm volatile(
        "mma.sync.aligned.m16n8k16.row.col.f32.f16.f16.f32 "
        "{%0,%1,%2,%3}, {%4,%5,%6,%7}, {%8,%9}, {%0,%1,%2,%3};"
        : "+f"(d[0]), "+f"(d[1]), "+f"(d[2]), "+f"(d[3])
        : "r"(a[0]), "r"(a[1]), "r"(a[2]), "r"(a[3]), "r"(b[0]), "r"(b[1]));
}
__device__ __forceinline__ void cp_async16(uint32_t smem_addr, const void* g) {
    asm volatile("cp.async.cg.shared.global [%0], [%1], 16;" :: "r"(smem_addr), "l"(g));
}
__device__ __forceinline__ void cp_async16z(uint32_t smem_addr, const void* g, int sz) {
    asm volatile("cp.async.cg.shared.global [%0], [%1], 16, %2;"
                 :: "r"(smem_addr), "l"(g), "r"(sz));
}
#define CP_COMMIT() asm volatile("cp.async.commit_group;")
#define CP_WAIT0()  asm volatile("cp.async.wait_group 0;" ::: "memory")

// ---------------------------------------------------------------------------
// Pre-kernel: split W into fp16 hi/lo.
// ---------------------------------------------------------------------------
__global__ void wsplit_kernel(const float* __restrict__ w_q,
                              const float* __restrict__ w_k)
{
    int idx = blockIdx.x * 256 + threadIdx.x;
    int row = idx >> 6;
    int c4  = (idx & 63) * 4;
    const float* src = (row < 128) ? &w_q[row * 256 + c4]
                                   : &w_k[(row - 128) * 256 + c4];
    float4 v = *(const float4*)src;
    uint2 h, l; split4(v, h, l);
    *(uint2*)&g_wh[row][c4] = h;
    *(uint2*)&g_wl[row][c4] = l;
}

// ---------------------------------------------------------------------------
// GEMM: per CTA ONE matrix, M=128, N=64 px, K=256 in 4 chunks of 64.
// NOW 512 threads, 16 warps = 4m x 4n, warp tile 32x16 -> 32 warps/SM at
// 2 CTAs/SM (same smem/tile/traffic as R15, double the latency hiding).
// Terms: W_hi*X_hi + W_lo*X_hi. W hi+lo via cp.async; X hi-only reg-prefetch.
// ---------------------------------------------------------------------------
#define ASTR_B  144
#define A_BYTES 18432
#define ABUF    36864                 // W hi + lo, one buffer
#define BSTR_B  144
#define B_BYTES 9216                  // X hi only, one buffer
#define BBASE   73728                 // 2 * ABUF
#define G_SMEM  92160                 // 2*ABUF + 2*B_BYTES
#define EPSTR   68

__global__ __launch_bounds__(512, 2) void qk_gemm_mma(const float* __restrict__ x)
{
    extern __shared__ char gsm[];
    const uint32_t sb = smem_u32(gsm);
    const int tid = threadIdx.x;
    const int wid = tid >> 5;
    const int lid = tid & 31;
    const int mw  = wid & 3;      // m block of 32
    const int nw  = wid >> 2;     // n block of 16

    const int mat = blockIdx.x;   // 0 = q, 1 = k (pair-adjacent with same tile)
    const int n0  = blockIdx.y * 64;
    const int b   = n0 / HWSZ;
    const int hw0 = n0 % HWSZ;
    const float* __restrict__ xb = x + (size_t)b * CIN * HWSZ + hw0;

    float acc[2][2][4];
#pragma unroll
    for (int mi = 0; mi < 2; mi++)
#pragma unroll
        for (int ni = 0; ni < 2; ni++)
#pragma unroll
            for (int c = 0; c < 4; c++) acc[mi][ni][c] = 0.0f;

    auto loadW = [&](int chunk, int buf) {
        int c0 = chunk * 64;
#pragma unroll
        for (int j = 0; j < 4; j++) {
            int pc  = tid + j * 512;      // 0..2047
            int sp  = pc >> 10;
            int rem = pc & 1023;
            int row = rem >> 3;
            int kp  = rem & 7;
            const __half* wsrc = sp ? &g_wl[mat * 128 + row][c0 + kp * 8]
                                    : &g_wh[mat * 128 + row][c0 + kp * 8];
            cp_async16(sb + buf * ABUF + sp * A_BYTES + row * ASTR_B + kp * 16, wsrc);
        }
        CP_COMMIT();
    };
    auto ldgX = [&](int chunk, float4* xr) {
        int c0 = chunk * 64;
#pragma unroll
        for (int j = 0; j < 2; j++) {
            int idx = tid + j * 512;      // 0..1023
            int ch  = idx >> 4;
            int p4  = (idx & 15) * 4;
            xr[j] = *(const float4*)&xb[(size_t)(c0 + ch) * HWSZ + p4];
        }
    };
    auto stsX = [&](const float4* xr, int buf) {
        char* bbase = gsm + BBASE + buf * B_BYTES;
#pragma unroll
        for (int j = 0; j < 2; j++) {
            int idx = tid + j * 512;
            int ch  = idx >> 4;
            int p4  = (idx & 15) * 4;
            *(uint2*)(bbase + ch * BSTR_B + p4 * 2) = hi4(xr[j]);
        }
    };

    float4 xr[2];
    loadW(0, 0);
    ldgX(0, xr);
    stsX(xr, 0);
    CP_WAIT0();
    __syncthreads();

    const int arow = (lid & 15);
    const int acol = (lid >> 4) * 16;

    for (int chunk = 0; chunk < 4; chunk++) {
        const int cur = chunk & 1;
        if (chunk < 3) {
            loadW(chunk + 1, cur ^ 1);
            ldgX(chunk + 1, xr);
        }
        const uint32_t ahb = sb + cur * ABUF;
        const uint32_t alb = ahb + A_BYTES;
        const uint32_t bhb = sb + BBASE + cur * B_BYTES;
#pragma unroll
        for (int kp = 0; kp < 2; kp++) {
            uint32_t bh[2][4];
#pragma unroll
            for (int ni = 0; ni < 2; ni++) {
                uint32_t bo = (uint32_t)((kp * 32 + lid) * BSTR_B + (nw * 16 + ni * 8) * 2);
                ldsm_x4t(bh[ni], bhb + bo);
            }
#pragma unroll
            for (int ks2 = 0; ks2 < 2; ks2++) {
                const int ks = kp * 2 + ks2;
                uint32_t ah[2][4], al[2][4];
#pragma unroll
                for (int mi = 0; mi < 2; mi++) {
                    uint32_t off = (uint32_t)((mw * 32 + mi * 16 + arow) * ASTR_B + ks * 32 + acol);
                    ldsm_x4(ah[mi], ahb + off);
                    ldsm_x4(al[mi], alb + off);
                }
#pragma unroll
                for (int ni = 0; ni < 2; ni++) {
#pragma unroll
                    for (int mi = 0; mi < 2; mi++) {
                        mma_f32(acc[mi][ni], ah[mi], bh[ni] + 2 * ks2);   // Whi*Xhi
                        mma_f32(acc[mi][ni], al[mi], bh[ni] + 2 * ks2);   // Wlo*Xhi
                    }
                }
            }
        }
        if (chunk < 3) {
            stsX(xr, cur ^ 1);
            CP_WAIT0();
        }
        __syncthreads();
    }

    // ---- epilogue: transpose through smem; q -> hi+lo, k -> hi only ----
    float* ep = (float*)gsm;
    {
        int chb = mw * 32 + (lid >> 2);
        int pxb = nw * 16 + (lid & 3) * 2;
#pragma unroll
        for (int mi = 0; mi < 2; mi++)
#pragma unroll
            for (int ni = 0; ni < 2; ni++) {
                int ch = chb + mi * 16;
                int px = pxb + ni * 8;
                *(float2*)&ep[ch * EPSTR + px]       = make_float2(acc[mi][ni][0], acc[mi][ni][1]);
                *(float2*)&ep[(ch + 8) * EPSTR + px] = make_float2(acc[mi][ni][2], acc[mi][ni][3]);
            }
    }
    __syncthreads();
    {
        __half* __restrict__ oh = mat ? g_kh : g_qh;
#pragma unroll
        for (int j = 0; j < 2; j++) {
            int i  = tid + j * 512;       // 0..1023
            int px = i & 63;
            int c8 = (i >> 6) * 8;
            uint32_t hp[4], lp[4];
#pragma unroll
            for (int t = 0; t < 4; t++) {
                float f0 = ep[(c8 + 2 * t) * EPSTR + px];
                float f1 = ep[(c8 + 2 * t + 1) * EPSTR + px];
                __half h0 = __float2half_rn(f0), h1 = __float2half_rn(f1);
                hp[t] = pack2(h0, h1);
                lp[t] = pack2(__float2half_rn(f0 - __half2float(h0)),
                              __float2half_rn(f1 - __half2float(h1)));
            }
            size_t base = (size_t)(n0 + px) * ACH + c8;
            *(uint4*)&oh[base] = make_uint4(hp[0], hp[1], hp[2], hp[3]);
            if (mat == 0)
                *(uint4*)&g_ql[base] = make_uint4(lp[0], lp[1], lp[2], lp[3]);
        }
    }
}

// ---------------------------------------------------------------------------
// Kernel 2: sim — unchanged from R14/R15.
// ---------------------------------------------------------------------------
#define TP     8
#define HALO   14
#define CSTRB  144
#define QSTR_B 272
#define SQH    0
#define SQL    17408
#define SKH    34816
#define SS_OFF 34816
#define SIM_SMEM 68608
#define SSTR2  132

__global__ __launch_bounds__(256, 3) void sim_mma(
    const float* __restrict__ rel_h,
    const float* __restrict__ rel_w,
    float* __restrict__ out)
{
    extern __shared__ char sm[];
    const uint32_t sb = smem_u32(sm);
    const int tid = threadIdx.x;
    const int wid = tid >> 5;
    const int lid = tid & 31;
    const int bb  = blockIdx.z;
    const int th0 = blockIdx.y * TP;
    const int tw0 = blockIdx.x * TP;

    const int blk = wid >> 1;
    const int nh  = wid & 1;

    float acc[8][4];
#pragma unroll
    for (int ni = 0; ni < 8; ni++)
#pragma unroll
        for (int c = 0; c < 4; c++) acc[ni][c] = 0.0f;

    const int arow = lid & 15;
    const int asel = (lid >> 4) * 16;
    const int brow = lid & 7;
    const int bgrp = ((lid >> 3) & 3) * 16;

    // Q fill, once, hi+lo, all 128 ch
#pragma unroll
    for (int j = 0; j < 8; j++) {
        int i = tid + j * 256;
        int s = i >> 10, rem = i & 1023, r = rem >> 4, c16 = rem & 15;
        int py = r >> 3, pxx = r & 7;
        size_t gp = (size_t)bb * HWSZ + (th0 + py) * WWID + (tw0 + pxx);
        const __half* src = (s ? g_ql : g_qh) + gp * ACH + c16 * 8;
        cp_async16(sb + (s ? SQL : SQH) + r * QSTR_B + c16 * 16, src);
    }

    // K halo fill: 196 rows x 8 chunks, hi only; all 256 threads
    const int kc16 = tid & 7;
    const int rseq = tid >> 3;                 // 0..31
    const uint32_t kdst0 = sb + SKH + rseq * CSTRB + kc16 * 16;

    for (int half = 0; half < 2; half++) {
        const int ch0 = half * 64;

        {
            int hy = (rseq >= 28) ? 2 : (rseq >= 14 ? 1 : 0);
            int hx = rseq - hy * HALO;
            uint32_t dst = kdst0;
            for (int r = rseq; r < 196; r += 32) {
                int gh = th0 + hy - 3, gw = tw0 + hx - 3;
                bool ok = ((unsigned)gh < HH) && ((unsigned)gw < WWID);
                size_t gp = ok ? ((size_t)bb * HWSZ + gh * WWID + gw) : 0;
                cp_async16z(dst, g_kh + gp * ACH + ch0 + kc16 * 8, ok ? 16 : 0);
                dst += 32 * CSTRB;
                hy += 2; hx += 4;
                if (hx >= HALO) { hx -= HALO; hy += 1; }
            }
        }
        CP_COMMIT();

        // bias rows 196..211 (hi only)
        for (int i = tid; i < 1024; i += 256) {
            int rl = i >> 6, ch = i & 63;
            float b = 0.0f;
            if (half == 0) { if (rl < 7) b = rel_h[ch * 7 + rl]; }
            else           { if (rl >= 8 && rl < 15) b = rel_w[ch * 7 + (rl - 8)]; }
            *(__half*)(sm + SKH + (196 + rl) * CSTRB + ch * 2) = __float2half_rn(b);
        }
        CP_WAIT0();
        __syncthreads();

#pragma unroll
        for (int kp = 0; kp < 2; kp++) {
            uint32_t ah[2][4], al[2][4];
#pragma unroll
            for (int ks2 = 0; ks2 < 2; ks2++) {
                uint32_t ao = (uint32_t)((blk * 16 + arow) * QSTR_B + half * 128 +
                                         (kp * 2 + ks2) * 32 + asel);
                ldsm_x4(ah[ks2], sb + SQH + ao);
                ldsm_x4(al[ks2], sb + SQL + ao);
            }
#pragma unroll
            for (int ni = 0; ni < 8; ni++) {
                int niG = nh * 8 + ni;
                int rbase = (niG < 14) ? (blk * 28 + niG * 8) : (196 + (niG - 14) * 8);
                uint32_t bo = (uint32_t)((rbase + brow) * CSTRB + kp * 64 + bgrp);
                uint32_t bh4[4];
                ldsm_x4(bh4, sb + SKH + bo);
                mma_f32(acc[ni], ah[0], bh4);        // qhi*khi (ks even)
                mma_f32(acc[ni], al[0], bh4);        // qlo*khi
                mma_f32(acc[ni], ah[1], bh4 + 2);    // ks odd
                mma_f32(acc[ni], al[1], bh4 + 2);
            }
        }
        __syncthreads();   // before next half's fills overwrite K tiles
    }

    float* S = (float*)(sm + SS_OFF);
    {
        float* Sb = S + blk * 16 * SSTR2;
        int m = lid >> 2;
        int n = nh * 64 + (lid & 3) * 2;
#pragma unroll
        for (int ni = 0; ni < 8; ni++) {
            *(float2*)&Sb[m * SSTR2 + n + ni * 8]       = make_float2(acc[ni][0], acc[ni][1]);
            *(float2*)&Sb[(m + 8) * SSTR2 + n + ni * 8] = make_float2(acc[ni][2], acc[ni][3]);
        }
    }
    __syncthreads();

    for (int i = tid; i < 64 * NOFF; i += 256) {
        int px = i / NOFF, o = i - px * NOFF;
        int oy = o / KWIN, ox = o - oy * KWIN;
        int py = px >> 3, pxx = px & 7;
        int bq = py >> 1, r = py & 1;
        const float* Sb = S + (bq * 16 + r * 8 + pxx) * SSTR2;
        float v = Sb[(oy + r) * HALO + pxx + ox] + Sb[112 + oy] + Sb[120 + ox];
        size_t gp = (size_t)bb * HWSZ + (th0 + py) * WWID + (tw0 + pxx);
        out[gp * NOFF + o] = v;
    }
}

// ---------------------------------------------------------------------------
extern "C" void kernel_launch(void* const* d_in, const int* in_sizes, int n_in,
                              void* d_out, int out_size)
{
    const float* x     = (const float*)d_in[0];
    const float* w_q   = (const float*)d_in[1];
    const float* w_k   = (const float*)d_in[2];
    const float* rel_h = (const float*)d_in[3];
    const float* rel_w = (const float*)d_in[4];
    float* out = (float*)d_out;

    cudaFuncSetAttribute(qk_gemm_mma, cudaFuncAttributeMaxDynamicSharedMemorySize, G_SMEM);
    cudaFuncSetAttribute(sim_mma,     cudaFuncAttributeMaxDynamicSharedMemorySize, SIM_SMEM);

    wsplit_kernel<<<64, 256>>>(w_q, w_k);

    dim3 g1(2, NPIX / 64);                 // pair-adjacent q/k CTAs
    qk_gemm_mma<<<g1, 512, G_SMEM>>>(x);

    dim3 g2(WWID / TP, HH / TP, BATCH);
    sim_mma<<<g2, 256, SIM_SMEM>>>(rel_h, rel_w, out);
}

// round 17
// speedup vs baseline: 1.0456x; 1.0456x over previous
#include <cuda_runtime.h>
#include <cuda_fp16.h>
#include <cstdint>

// ---------------- problem constants ----------------
#define HH    96
#define WWID  96
#define HWSZ  (HH * WWID)      // 9216
#define BATCH 8
#define CIN   256
#define ACH   128
#define KWIN  7
#define NOFF  (KWIN * KWIN)    // 49
#define NPIX  (BATCH * HWSZ)   // 73728

// q scratch fp16 hi/lo; k scratch fp16 hi only
__device__ __half g_qh[(size_t)NPIX * ACH];
__device__ __half g_ql[(size_t)NPIX * ACH];
__device__ __half g_kh[(size_t)NPIX * ACH];

// W split into fp16 hi/lo, rows 0-127 = w_q, rows 128-255 = w_k
__device__ __half g_wh[256][256];
__device__ __half g_wl[256][256];

// ---------------- helpers ----------------
__device__ __forceinline__ uint32_t smem_u32(const void* p) {
    uint32_t a;
    asm("{ .reg .u64 t; cvta.to.shared.u64 t, %1; cvt.u32.u64 %0, t; }"
        : "=r"(a) : "l"(p));
    return a;
}

__device__ __forceinline__ uint32_t pack2(__half a, __half b) {
    return (uint32_t)__half_as_ushort(a) | ((uint32_t)__half_as_ushort(b) << 16);
}

__device__ __forceinline__ void split4(float4 v, uint2& hi, uint2& lo) {
    __half h0 = __float2half_rn(v.x), h1 = __float2half_rn(v.y);
    __half h2 = __float2half_rn(v.z), h3 = __float2half_rn(v.w);
    __half l0 = __float2half_rn(v.x - __half2float(h0));
    __half l1 = __float2half_rn(v.y - __half2float(h1));
    __half l2 = __float2half_rn(v.z - __half2float(h2));
    __half l3 = __float2half_rn(v.w - __half2float(h3));
    hi = make_uint2(pack2(h0, h1), pack2(h2, h3));
    lo = make_uint2(pack2(l0, l1), pack2(l2, l3));
}
__device__ __forceinline__ uint2 hi4(float4 v) {
    return make_uint2(pack2(__float2half_rn(v.x), __float2half_rn(v.y)),
                      pack2(__float2half_rn(v.z), __float2half_rn(v.w)));
}

__device__ __forceinline__ void ldsm_x4(uint32_t* r, uint32_t addr) {
    asm volatile("ldmatrix.sync.aligned.m8n8.x4.shared.b16 {%0,%1,%2,%3}, [%4];"
                 : "=r"(r[0]), "=r"(r[1]), "=r"(r[2]), "=r"(r[3]) : "r"(addr));
}
__device__ __forceinline__ void ldsm_x4t(uint32_t* r, uint32_t addr) {
    asm volatile("ldmatrix.sync.aligned.m8n8.x4.trans.shared.b16 {%0,%1,%2,%3}, [%4];"
                 : "=r"(r[0]), "=r"(r[1]), "=r"(r[2]), "=r"(r[3]) : "r"(addr));
}
__device__ __forceinline__ void mma_f32(float* d, const uint32_t* a, const uint32_t* b) {
    asm volatile(
        "mma.sync.aligned.m16n8k16.row.col.f32.f16.f16.f32 "
        "{%0,%1,%2,%3}, {%4,%5,%6,%7}, {%8,%9}, {%0,%1,%2,%3};"
        : "+f"(d[0]), "+f"(d[1]), "+f"(d[2]), "+f"(d[3])
        : "r"(a[0]), "r"(a[1]), "r"(a[2]), "r"(a[3]), "r"(b[0]), "r"(b[1]));
}
__device__ __forceinline__ void cp_async16(uint32_t smem_addr, const void* g) {
    asm volatile("cp.async.cg.shared.global [%0], [%1], 16;" :: "r"(smem_addr), "l"(g));
}
__device__ __forceinline__ void cp_async16z(uint32_t smem_addr, const void* g, int sz) {
    asm volatile("cp.async.cg.shared.global [%0], [%1], 16, %2;"
                 :: "r"(smem_addr), "l"(g), "r"(sz));
}
#define CP_COMMIT() asm volatile("cp.async.commit_group;")
#define CP_WAIT0()  asm volatile("cp.async.wait_group 0;" ::: "memory")

// ---------------------------------------------------------------------------
// Pre-kernel: split W into fp16 hi/lo.
// ---------------------------------------------------------------------------
__global__ void wsplit_kernel(const float* __restrict__ w_q,
                              const float* __restrict__ w_k)
{
    int idx = blockIdx.x * 256 + threadIdx.x;
    int row = idx >> 6;
    int c4  = (idx & 63) * 4;
    const float* src = (row < 128) ? &w_q[row * 256 + c4]
                                   : &w_k[(row - 128) * 256 + c4];
    float4 v = *(const float4*)src;
    uint2 h, l; split4(v, h, l);
    *(uint2*)&g_wh[row][c4] = h;
    *(uint2*)&g_wl[row][c4] = l;
}

// ---------------------------------------------------------------------------
// GEMM (R15 config): per CTA ONE matrix, M=128, N=64 px, K=256 in 4 chunks
// of 64. 256 threads, 8 warps = 4m x 2n (warp tile 32x32), 2 CTAs/SM.
// Terms: W_hi*X_hi + W_lo*X_hi. W hi+lo via cp.async double-buffered.
// NEW: X store (stsX) software-pipelined to the TOP of the compute phase
// (X LDG prefetch distance 2), so the STS drain overlaps the mma stream and
// the post-compute tail is just the W-wait + sync.
// ---------------------------------------------------------------------------
#define ASTR_B  144
#define A_BYTES 18432
#define ABUF    36864                 // W hi + lo, one buffer
#define BSTR_B  144
#define B_BYTES 9216                  // X hi only, one buffer
#define BBASE   73728                 // 2 * ABUF
#define G_SMEM  92160                 // 2*ABUF + 2*B_BYTES
#define EPSTR   68

__global__ __launch_bounds__(256, 2) void qk_gemm_mma(const float* __restrict__ x)
{
    extern __shared__ char gsm[];
    const uint32_t sb = smem_u32(gsm);
    const int tid = threadIdx.x;
    const int wid = tid >> 5;
    const int lid = tid & 31;
    const int mw  = wid & 3;
    const int nw  = wid >> 2;

    const int mat = blockIdx.x;   // 0 = q, 1 = k (pair-adjacent with same tile)
    const int n0  = blockIdx.y * 64;
    const int b   = n0 / HWSZ;
    const int hw0 = n0 % HWSZ;
    const float* __restrict__ xb = x + (size_t)b * CIN * HWSZ + hw0;

    float acc[2][4][4];
#pragma unroll
    for (int mi = 0; mi < 2; mi++)
#pragma unroll
        for (int ni = 0; ni < 4; ni++)
#pragma unroll
            for (int c = 0; c < 4; c++) acc[mi][ni][c] = 0.0f;

    auto loadW = [&](int chunk, int buf) {
        int c0 = chunk * 64;
#pragma unroll
        for (int j = 0; j < 8; j++) {
            int pc  = tid + j * 256;
            int sp  = pc >> 10;
            int rem = pc & 1023;
            int row = rem >> 3;
            int kp  = rem & 7;
            const __half* wsrc = sp ? &g_wl[mat * 128 + row][c0 + kp * 8]
                                    : &g_wh[mat * 128 + row][c0 + kp * 8];
            cp_async16(sb + buf * ABUF + sp * A_BYTES + row * ASTR_B + kp * 16, wsrc);
        }
        CP_COMMIT();
    };
    auto ldgX = [&](int chunk, float4* xr) {
        int c0 = chunk * 64;
#pragma unroll
        for (int j = 0; j < 4; j++) {
            int idx = tid + j * 256;
            int ch  = idx >> 4;
            int p4  = (idx & 15) * 4;
            xr[j] = *(const float4*)&xb[(size_t)(c0 + ch) * HWSZ + p4];
        }
    };
    auto stsX = [&](const float4* xr, int buf) {
        char* bbase = gsm + BBASE + buf * B_BYTES;
#pragma unroll
        for (int j = 0; j < 4; j++) {
            int idx = tid + j * 256;
            int ch  = idx >> 4;
            int p4  = (idx & 15) * 4;
            *(uint2*)(bbase + ch * BSTR_B + p4 * 2) = hi4(xr[j]);
        }
    };

    // prologue: X0 -> buf0, X1 -> regs, W0 -> buf0
    float4 xr[4];
    loadW(0, 0);
    ldgX(0, xr);
    stsX(xr, 0);
    ldgX(1, xr);          // xr now holds X(1)
    CP_WAIT0();
    __syncthreads();

    const int arow = (lid & 15);
    const int acol = (lid >> 4) * 16;

    for (int chunk = 0; chunk < 4; chunk++) {
        const int cur = chunk & 1;
        if (chunk < 3) {
            stsX(xr, cur ^ 1);          // X(chunk+1) fp16 -> alt buffer (drains under compute)
            loadW(chunk + 1, cur ^ 1);  // W(chunk+1) cp.async -> alt buffer
        }
        if (chunk < 2) ldgX(chunk + 2, xr);   // X(chunk+2) fp32 -> regs
        const uint32_t ahb = sb + cur * ABUF;
        const uint32_t alb = ahb + A_BYTES;
        const uint32_t bhb = sb + BBASE + cur * B_BYTES;
#pragma unroll
        for (int kp = 0; kp < 2; kp++) {
            uint32_t bh[4][4];
#pragma unroll
            for (int ni = 0; ni < 4; ni++) {
                uint32_t bo = (uint32_t)((kp * 32 + lid) * BSTR_B + (nw * 32 + ni * 8) * 2);
                ldsm_x4t(bh[ni], bhb + bo);
            }
#pragma unroll
            for (int ks2 = 0; ks2 < 2; ks2++) {
                const int ks = kp * 2 + ks2;
                uint32_t ah[2][4], al[2][4];
#pragma unroll
                for (int mi = 0; mi < 2; mi++) {
                    uint32_t off = (uint32_t)((mw * 32 + mi * 16 + arow) * ASTR_B + ks * 32 + acol);
                    ldsm_x4(ah[mi], ahb + off);
                    ldsm_x4(al[mi], alb + off);
                }
#pragma unroll
                for (int ni = 0; ni < 4; ni++) {
#pragma unroll
                    for (int mi = 0; mi < 2; mi++) {
                        mma_f32(acc[mi][ni], ah[mi], bh[ni] + 2 * ks2);   // Whi*Xhi
                        mma_f32(acc[mi][ni], al[mi], bh[ni] + 2 * ks2);   // Wlo*Xhi
                    }
                }
            }
        }
        if (chunk < 3) CP_WAIT0();
        __syncthreads();
    }

    // ---- epilogue: transpose through smem; q -> hi+lo, k -> hi only ----
    float* ep = (float*)gsm;
    {
        int chb = mw * 32 + (lid >> 2);
        int pxb = nw * 32 + (lid & 3) * 2;
#pragma unroll
        for (int mi = 0; mi < 2; mi++)
#pragma unroll
            for (int ni = 0; ni < 4; ni++) {
                int ch = chb + mi * 16;
                int px = pxb + ni * 8;
                *(float2*)&ep[ch * EPSTR + px]       = make_float2(acc[mi][ni][0], acc[mi][ni][1]);
                *(float2*)&ep[(ch + 8) * EPSTR + px] = make_float2(acc[mi][ni][2], acc[mi][ni][3]);
            }
    }
    __syncthreads();
    {
        __half* __restrict__ oh = mat ? g_kh : g_qh;
#pragma unroll
        for (int j = 0; j < 4; j++) {
            int i  = tid + j * 256;
            int px = i & 63;
            int c8 = (i >> 6) * 8;
            uint32_t hp[4], lp[4];
#pragma unroll
            for (int t = 0; t < 4; t++) {
                float f0 = ep[(c8 + 2 * t) * EPSTR + px];
                float f1 = ep[(c8 + 2 * t + 1) * EPSTR + px];
                __half h0 = __float2half_rn(f0), h1 = __float2half_rn(f1);
                hp[t] = pack2(h0, h1);
                lp[t] = pack2(__float2half_rn(f0 - __half2float(h0)),
                              __float2half_rn(f1 - __half2float(h1)));
            }
            size_t base = (size_t)(n0 + px) * ACH + c8;
            *(uint4*)&oh[base] = make_uint4(hp[0], hp[1], hp[2], hp[3]);
            if (mat == 0)
                *(uint4*)&g_ql[base] = make_uint4(lp[0], lp[1], lp[2], lp[3]);
        }
    }
}

// ---------------------------------------------------------------------------
// Kernel 2: sim — unchanged from R14/R15 (champion config).
// ---------------------------------------------------------------------------
#define TP     8
#define HALO   14
#define CSTRB  144
#define QSTR_B 272
#define SQH    0
#define SQL    17408
#define SKH    34816
#define SS_OFF 34816
#define SIM_SMEM 68608
#define SSTR2  132

__global__ __launch_bounds__(256, 3) void sim_mma(
    const float* __restrict__ rel_h,
    const float* __restrict__ rel_w,
    float* __restrict__ out)
{
    extern __shared__ char sm[];
    const uint32_t sb = smem_u32(sm);
    const int tid = threadIdx.x;
    const int wid = tid >> 5;
    const int lid = tid & 31;
    const int bb  = blockIdx.z;
    const int th0 = blockIdx.y * TP;
    const int tw0 = blockIdx.x * TP;

    const int blk = wid >> 1;
    const int nh  = wid & 1;

    float acc[8][4];
#pragma unroll
    for (int ni = 0; ni < 8; ni++)
#pragma unroll
        for (int c = 0; c < 4; c++) acc[ni][c] = 0.0f;

    const int arow = lid & 15;
    const int asel = (lid >> 4) * 16;
    const int brow = lid & 7;
    const int bgrp = ((lid >> 3) & 3) * 16;

    // Q fill, once, hi+lo, all 128 ch
#pragma unroll
    for (int j = 0; j < 8; j++) {
        int i = tid + j * 256;
        int s = i >> 10, rem = i & 1023, r = rem >> 4, c16 = rem & 15;
        int py = r >> 3, pxx = r & 7;
        size_t gp = (size_t)bb * HWSZ + (th0 + py) * WWID + (tw0 + pxx);
        const __half* src = (s ? g_ql : g_qh) + gp * ACH + c16 * 8;
        cp_async16(sb + (s ? SQL : SQH) + r * QSTR_B + c16 * 16, src);
    }

    // K halo fill: 196 rows x 8 chunks, hi only; all 256 threads
    const int kc16 = tid & 7;
    const int rseq = tid >> 3;                 // 0..31
    const uint32_t kdst0 = sb + SKH + rseq * CSTRB + kc16 * 16;

    for (int half = 0; half < 2; half++) {
        const int ch0 = half * 64;

        {
            int hy = (rseq >= 28) ? 2 : (rseq >= 14 ? 1 : 0);
            int hx = rseq - hy * HALO;
            uint32_t dst = kdst0;
            for (int r = rseq; r < 196; r += 32) {
                int gh = th0 + hy - 3, gw = tw0 + hx - 3;
                bool ok = ((unsigned)gh < HH) && ((unsigned)gw < WWID);
                size_t gp = ok ? ((size_t)bb * HWSZ + gh * WWID + gw) : 0;
                cp_async16z(dst, g_kh + gp * ACH + ch0 + kc16 * 8, ok ? 16 : 0);
                dst += 32 * CSTRB;
                hy += 2; hx += 4;
                if (hx >= HALO) { hx -= HALO; hy += 1; }
            }
        }
        CP_COMMIT();

        // bias rows 196..211 (hi only)
        for (int i = tid; i < 1024; i += 256) {
            int rl = i >> 6, ch = i & 63;
            float b = 0.0f;
            if (half == 0) { if (rl < 7) b = rel_h[ch * 7 + rl]; }
            else           { if (rl >= 8 && rl < 15) b = rel_w[ch * 7 + (rl - 8)]; }
            *(__half*)(sm + SKH + (196 + rl) * CSTRB + ch * 2) = __float2half_rn(b);
        }
        CP_WAIT0();
        __syncthreads();

#pragma unroll
        for (int kp = 0; kp < 2; kp++) {
            uint32_t ah[2][4], al[2][4];
#pragma unroll
            for (int ks2 = 0; ks2 < 2; ks2++) {
                uint32_t ao = (uint32_t)((blk * 16 + arow) * QSTR_B + half * 128 +
                                         (kp * 2 + ks2) * 32 + asel);
                ldsm_x4(ah[ks2], sb + SQH + ao);
                ldsm_x4(al[ks2], sb + SQL + ao);
            }
#pragma unroll
            for (int ni = 0; ni < 8; ni++) {
                int niG = nh * 8 + ni;
                int rbase = (niG < 14) ? (blk * 28 + niG * 8) : (196 + (niG - 14) * 8);
                uint32_t bo = (uint32_t)((rbase + brow) * CSTRB + kp * 64 + bgrp);
                uint32_t bh4[4];
                ldsm_x4(bh4, sb + SKH + bo);
                mma_f32(acc[ni], ah[0], bh4);        // qhi*khi (ks even)
                mma_f32(acc[ni], al[0], bh4);        // qlo*khi
                mma_f32(acc[ni], ah[1], bh4 + 2);    // ks odd
                mma_f32(acc[ni], al[1], bh4 + 2);
            }
        }
        __syncthreads();   // before next half's fills overwrite K tiles
    }

    float* S = (float*)(sm + SS_OFF);
    {
        float* Sb = S + blk * 16 * SSTR2;
        int m = lid >> 2;
        int n = nh * 64 + (lid & 3) * 2;
#pragma unroll
        for (int ni = 0; ni < 8; ni++) {
            *(float2*)&Sb[m * SSTR2 + n + ni * 8]       = make_float2(acc[ni][0], acc[ni][1]);
            *(float2*)&Sb[(m + 8) * SSTR2 + n + ni * 8] = make_float2(acc[ni][2], acc[ni][3]);
        }
    }
    __syncthreads();

    for (int i = tid; i < 64 * NOFF; i += 256) {
        int px = i / NOFF, o = i - px * NOFF;
        int oy = o / KWIN, ox = o - oy * KWIN;
        int py = px >> 3, pxx = px & 7;
        int bq = py >> 1, r = py & 1;
        const float* Sb = S + (bq * 16 + r * 8 + pxx) * SSTR2;
        float v = Sb[(oy + r) * HALO + pxx + ox] + Sb[112 + oy] + Sb[120 + ox];
        size_t gp = (size_t)bb * HWSZ + (th0 + py) * WWID + (tw0 + pxx);
        out[gp * NOFF + o] = v;
    }
}

// ---------------------------------------------------------------------------
extern "C" void kernel_launch(void* const* d_in, const int* in_sizes, int n_in,
                              void* d_out, int out_size)
{
    const float* x     = (const float*)d_in[0];
    const float* w_q   = (const float*)d_in[1];
    const float* w_k   = (const float*)d_in[2];
    const float* rel_h = (const float*)d_in[3];
    const float* rel_w = (const float*)d_in[4];
    float* out = (float*)d_out;

    cudaFuncSetAttribute(qk_gemm_mma, cudaFuncAttributeMaxDynamicSharedMemorySize, G_SMEM);
    cudaFuncSetAttribute(sim_mma,     cudaFuncAttributeMaxDynamicSharedMemorySize, SIM_SMEM);

    wsplit_kernel<<<64, 256>>>(w_q, w_k);

    dim3 g1(2, NPIX / 64);                 // pair-adjacent q/k CTAs
    qk_gemm_mma<<<g1, 256, G_SMEM>>>(x);

    dim3 g2(WWID / TP, HH / TP, BATCH);
    sim_mma<<<g2, 256, SIM_SMEM>>>(rel_h, rel_w, out);
}